// round 8
// baseline (speedup 1.0000x reference)
#include <cuda_runtime.h>
#include <cstdint>

#define T_ 128
#define V_ 5023
#define K_ 16
#define NTV (T_ * V_)
#define THREADS 1024

extern __shared__ float s_rec[];  // [6 * V_] : {can.xyz, def.xyz} per vertex

__global__ void __launch_bounds__(THREADS)
se3_frame_kernel(const float* __restrict__ can, const float* __restrict__ def,
                 const int* __restrict__ nbr, const void* __restrict__ maskp,
                 float* __restrict__ out) {
    const int t = blockIdx.x;
    const int tid = threadIdx.x;
    const float* canT = can + (size_t)t * (V_ * 3);
    const float* defT = def + (size_t)t * (V_ * 3);

    __shared__ int s_mode;  // 0 = uint8 bool, 1 = int32, 2 = float32

    // ---- inline mask dtype detection (warp 0, first 32 words) ----
    if (tid < 32) {
        unsigned int x = ((const unsigned int*)maskp)[tid];
        bool weird = (x != 0u) && (x != 1u) && (x != 0x3F800000u);
        bool isf32 = (x == 0x3F800000u);
        unsigned bp = __ballot_sync(0xffffffffu, weird);
        unsigned fp = __ballot_sync(0xffffffffu, isf32);
        if (tid == 0) s_mode = bp ? 0 : (fp ? 2 : 1);
    }

    // ---- stage this frame's positions into smem as packed 24B records ----
    for (int v = tid; v < V_; v += THREADS) {
        int b = 3 * v;
        float* r = s_rec + 6 * v;
        r[0] = canT[b]; r[1] = canT[b + 1]; r[2] = canT[b + 2];
        r[3] = defT[b]; r[4] = defT[b + 1]; r[5] = defT[b + 2];
    }
    __syncthreads();

    const int mode = s_mode;
    float* outt = out + (size_t)NTV * 4;

    for (int v = tid; v < V_; v += THREADS) {
        // ---- active-neighbor bitmask (dtype-robust) ----
        unsigned int amask = 0;
        if (mode == 0) {
            uint4 mw = *(const uint4*)((const unsigned char*)maskp + (size_t)v * K_);
            unsigned int ws[4] = {mw.x, mw.y, mw.z, mw.w};
#pragma unroll
            for (int i = 0; i < K_; i++)
                if ((ws[i >> 2] >> ((i & 3) * 8)) & 0xFF) amask |= (1u << i);
        } else if (mode == 1) {
            const int4* mi = (const int4*)((const int*)maskp + (size_t)v * K_);
#pragma unroll
            for (int c = 0; c < 4; c++) {
                int4 x = mi[c];
                if (x.x) amask |= 1u << (c * 4 + 0);
                if (x.y) amask |= 1u << (c * 4 + 1);
                if (x.z) amask |= 1u << (c * 4 + 2);
                if (x.w) amask |= 1u << (c * 4 + 3);
            }
        } else {
            const float4* mf = (const float4*)((const float*)maskp + (size_t)v * K_);
#pragma unroll
            for (int c = 0; c < 4; c++) {
                float4 x = mf[c];
                if (x.x != 0.0f) amask |= 1u << (c * 4 + 0);
                if (x.y != 0.0f) amask |= 1u << (c * 4 + 1);
                if (x.z != 0.0f) amask |= 1u << (c * 4 + 2);
                if (x.w != 0.0f) amask |= 1u << (c * 4 + 3);
            }
        }

        const float* rv = s_rec + 6 * v;
        float cx = rv[0], cy = rv[1], cz = rv[2];
        float dx = rv[3], dy = rv[4], dz = rv[5];

        // ---- masked gather sums over ACTIVE neighbors only ----
        float G1x = 0, G1y = 0, G1z = 0;
        float G2x = 0, G2y = 0, G2z = 0;
        float G300 = 0, G301 = 0, G302 = 0;
        float G310 = 0, G311 = 0, G312 = 0;
        float G320 = 0, G321 = 0, G322 = 0;

        const int4* ni = (const int4*)(nbr + (size_t)v * K_);
        // batch-4: issue all 12 LDS before consuming; nb chunk loaded per batch
#pragma unroll
        for (int c = 0; c < 4; c++) {
            int4 nbc = ni[c];
            unsigned sub = (amask >> (c * 4)) & 0xF;
            bool a0 = sub & 1u, a1_ = sub & 2u, a2_ = sub & 4u, a3_ = sub & 8u;
            float2 r0a, r1a, r2a, r0b, r1b, r2b;
            float2 r0c, r1c, r2c, r0d, r1d, r2d;
            if (a0) {
                const float2* rj = (const float2*)(s_rec + 6 * nbc.x);
                r0a = rj[0]; r1a = rj[1]; r2a = rj[2];
            }
            if (a1_) {
                const float2* rj = (const float2*)(s_rec + 6 * nbc.y);
                r0b = rj[0]; r1b = rj[1]; r2b = rj[2];
            }
            if (a2_) {
                const float2* rj = (const float2*)(s_rec + 6 * nbc.z);
                r0c = rj[0]; r1c = rj[1]; r2c = rj[2];
            }
            if (a3_) {
                const float2* rj = (const float2*)(s_rec + 6 * nbc.w);
                r0d = rj[0]; r1d = rj[1]; r2d = rj[2];
            }
            if (a0) {
                float px = r0a.x, py = r0a.y, pz = r1a.x;
                float qx = r1a.y, qy = r2a.x, qz = r2a.y;
                G1x += px; G1y += py; G1z += pz;
                G2x += qx; G2y += qy; G2z += qz;
                G300 = fmaf(qx, px, G300); G301 = fmaf(qx, py, G301); G302 = fmaf(qx, pz, G302);
                G310 = fmaf(qy, px, G310); G311 = fmaf(qy, py, G311); G312 = fmaf(qy, pz, G312);
                G320 = fmaf(qz, px, G320); G321 = fmaf(qz, py, G321); G322 = fmaf(qz, pz, G322);
            }
            if (a1_) {
                float px = r0b.x, py = r0b.y, pz = r1b.x;
                float qx = r1b.y, qy = r2b.x, qz = r2b.y;
                G1x += px; G1y += py; G1z += pz;
                G2x += qx; G2y += qy; G2z += qz;
                G300 = fmaf(qx, px, G300); G301 = fmaf(qx, py, G301); G302 = fmaf(qx, pz, G302);
                G310 = fmaf(qy, px, G310); G311 = fmaf(qy, py, G311); G312 = fmaf(qy, pz, G312);
                G320 = fmaf(qz, px, G320); G321 = fmaf(qz, py, G321); G322 = fmaf(qz, pz, G322);
            }
            if (a2_) {
                float px = r0c.x, py = r0c.y, pz = r1c.x;
                float qx = r1c.y, qy = r2c.x, qz = r2c.y;
                G1x += px; G1y += py; G1z += pz;
                G2x += qx; G2y += qy; G2z += qz;
                G300 = fmaf(qx, px, G300); G301 = fmaf(qx, py, G301); G302 = fmaf(qx, pz, G302);
                G310 = fmaf(qy, px, G310); G311 = fmaf(qy, py, G311); G312 = fmaf(qy, pz, G312);
                G320 = fmaf(qz, px, G320); G321 = fmaf(qz, py, G321); G322 = fmaf(qz, pz, G322);
            }
            if (a3_) {
                float px = r0d.x, py = r0d.y, pz = r1d.x;
                float qx = r1d.y, qy = r2d.x, qz = r2d.y;
                G1x += px; G1y += py; G1z += pz;
                G2x += qx; G2y += qy; G2z += qz;
                G300 = fmaf(qx, px, G300); G301 = fmaf(qx, py, G301); G302 = fmaf(qx, pz, G302);
                G310 = fmaf(qy, px, G310); G311 = fmaf(qy, py, G311); G312 = fmaf(qy, pz, G312);
                G320 = fmaf(qz, px, G320); G321 = fmaf(qz, py, G321); G322 = fmaf(qz, pz, G322);
            }
        }

        // A[i][j] = G3[i][j] - G2_i*c_j - d_i*(G1_j - 16*c_j)
        float Hx = fmaf(-16.0f, cx, G1x);
        float Hy = fmaf(-16.0f, cy, G1y);
        float Hz = fmaf(-16.0f, cz, G1z);
        float A00 = G300 - G2x * cx - dx * Hx;
        float A01 = G301 - G2x * cy - dx * Hy;
        float A02 = G302 - G2x * cz - dx * Hz;
        float A10 = G310 - G2y * cx - dy * Hx;
        float A11 = G311 - G2y * cy - dy * Hy;
        float A12 = G312 - G2y * cz - dy * Hz;
        float A20 = G320 - G2z * cx - dz * Hx;
        float A21 = G321 - G2z * cy - dz * Hy;
        float A22 = G322 - G2z * cz - dz * Hz;

        // ---- Davenport K matrix (symmetric, trace 0) ----
        float k00 = A00 + A11 + A22;
        float k11 = A00 - A11 - A22;
        float k22 = -A00 + A11 - A22;
        float k33 = -A00 - A11 + A22;
        float k01 = A21 - A12;
        float k02 = A02 - A20;
        float k03 = A10 - A01;
        float k12 = A01 + A10;
        float k13 = A02 + A20;
        float k23 = A12 + A21;

        // ---- characteristic quartic: f(x) = x^4 + c2 x^2 + c1 x + c0 ----
        float trAtA = A00 * A00 + A01 * A01 + A02 * A02 +
                      A10 * A10 + A11 * A11 + A12 * A12 +
                      A20 * A20 + A21 * A21 + A22 * A22;
        float c2 = -2.0f * trAtA;
        float detA = A00 * (A11 * A22 - A12 * A21)
                   - A01 * (A10 * A22 - A12 * A20)
                   + A02 * (A10 * A21 - A11 * A20);
        float c1 = -8.0f * detA;
        float M0 = k11 * (k22 * k33 - k23 * k23)
                 - k12 * (k12 * k33 - k23 * k13)
                 + k13 * (k12 * k23 - k22 * k13);
        float M1 = k01 * (k22 * k33 - k23 * k23)
                 - k12 * (k02 * k33 - k23 * k03)
                 + k13 * (k02 * k23 - k22 * k03);
        float M2 = k01 * (k12 * k33 - k23 * k13)
                 - k11 * (k02 * k33 - k23 * k03)
                 + k13 * (k02 * k13 - k12 * k03);
        float M3 = k01 * (k12 * k23 - k22 * k13)
                 - k11 * (k02 * k23 - k22 * k03)
                 + k12 * (k02 * k13 - k12 * k03);
        float c0 = k00 * M0 - k01 * M1 + k02 * M2 - k03 * M3;

        // ---- Newton from upper bound lam0 = sqrt(3 * tr(A^T A)) >= lam_max ----
        float lam = 1.7320508f * sqrtf(trAtA);
        float fp2 = 1.0f;
#pragma unroll
        for (int it = 0; it < 5; it++) {
            float lam2 = lam * lam;
            float f = (lam2 + c2) * lam2 + fmaf(c1, lam, c0);
            fp2 = fmaf(4.0f * lam2 + 2.0f * c2, lam, c1);
            lam -= __fdividef(f, fp2);
        }

        // ---- eigenvector: column 0 of M = B^3 + a3 B^2 + a2 B + a1 I ----
        float b00 = k00 - lam, b11 = k11 - lam, b22 = k22 - lam, b33 = k33 - lam;
        float a3 = 4.0f * lam;
        float a2 = fmaf(6.0f * lam, lam, c2);
        float a1 = fp2;

        float u10 = b00, u11 = k01, u12 = k02, u13 = k03;
        float u20 = b00 * u10 + k01 * u11 + k02 * u12 + k03 * u13;
        float u21 = k01 * u10 + b11 * u11 + k12 * u12 + k13 * u13;
        float u22 = k02 * u10 + k12 * u11 + b22 * u12 + k23 * u13;
        float u23 = k03 * u10 + k13 * u11 + k23 * u12 + b33 * u13;
        float u30 = b00 * u20 + k01 * u21 + k02 * u22 + k03 * u23;
        float u31 = k01 * u20 + b11 * u21 + k12 * u22 + k13 * u23;
        float u32 = k02 * u20 + k12 * u21 + b22 * u22 + k23 * u23;
        float u33 = k03 * u20 + k13 * u21 + k23 * u22 + b33 * u23;

        float qw = u30 + a3 * u20 + a2 * u10 + a1;
        float qx = u31 + a3 * u21 + a2 * u11;
        float qy = u32 + a3 * u22 + a2 * u12;
        float qz = u33 + a3 * u23 + a2 * u13;

        float nq = fmaf(qw, qw, fmaf(qx, qx, fmaf(qy, qy, qz * qz)));
        if (nq < 1e-4f * a1 * a1) {
            // rare fallback (near-180-degree rotation): full adjugate, best column
            float C00 = b00 * b00 + k01 * k01 + k02 * k02 + k03 * k03;
            float C01 = b00 * k01 + k01 * b11 + k02 * k12 + k03 * k13;
            float C02 = b00 * k02 + k01 * k12 + k02 * b22 + k03 * k23;
            float C03 = b00 * k03 + k01 * k13 + k02 * k23 + k03 * b33;
            float C11 = k01 * k01 + b11 * b11 + k12 * k12 + k13 * k13;
            float C12 = k01 * k02 + b11 * k12 + k12 * b22 + k13 * k23;
            float C13 = k01 * k03 + b11 * k13 + k12 * k23 + k13 * b33;
            float C22 = k02 * k02 + k12 * k12 + b22 * b22 + k23 * k23;
            float C23 = k02 * k03 + k12 * k13 + b22 * k23 + k23 * b33;
            float C33 = k03 * k03 + k13 * k13 + k23 * k23 + b33 * b33;
            float P01v = b00 * C01 + k01 * C11 + k02 * C12 + k03 * C13;
            float P02v = b00 * C02 + k01 * C12 + k02 * C22 + k03 * C23;
            float P03v = b00 * C03 + k01 * C13 + k02 * C23 + k03 * C33;
            float P11v = k01 * C01 + b11 * C11 + k12 * C12 + k13 * C13;
            float P12v = k01 * C02 + b11 * C12 + k12 * C22 + k13 * C23;
            float P13v = k01 * C03 + b11 * C13 + k12 * C23 + k13 * C33;
            float P22v = k02 * C02 + k12 * C12 + b22 * C22 + k23 * C23;
            float P23v = k02 * C03 + k12 * C13 + b22 * C23 + k23 * C33;
            float P33v = k03 * C03 + k13 * C13 + k23 * C23 + b33 * C33;
            float N01 = P01v + a3 * C01 + a2 * k01;
            float N02 = P02v + a3 * C02 + a2 * k02;
            float N03 = P03v + a3 * C03 + a2 * k03;
            float N11 = P11v + a3 * C11 + a2 * b11 + a1;
            float N12 = P12v + a3 * C12 + a2 * k12;
            float N13 = P13v + a3 * C13 + a2 * k13;
            float N22 = P22v + a3 * C22 + a2 * b22 + a1;
            float N23 = P23v + a3 * C23 + a2 * k23;
            float N33 = P33v + a3 * C33 + a2 * b33 + a1;
            float bd = nq > 0 ? sqrtf(nq) : 0.0f;
            if (fabsf(N11) > bd) { bd = fabsf(N11); qw = N01; qx = N11; qy = N12; qz = N13; }
            if (fabsf(N22) > bd) { bd = fabsf(N22); qw = N02; qx = N12; qy = N22; qz = N23; }
            if (fabsf(N33) > bd) { qw = N03; qx = N13; qy = N23; qz = N33; }
        }

        // sign convention: component with largest |value| (w,x,y,z, first on ties) positive
        float aw = fabsf(qw), ax = fabsf(qx), ay = fabsf(qy), az = fabsf(qz);
        float besta = aw, piv = qw;
        if (ax > besta) { besta = ax; piv = qx; }
        if (ay > besta) { besta = ay; piv = qy; }
        if (az > besta) { besta = az; piv = qz; }
        float invn = rsqrtf(fmaf(qw, qw, fmaf(qx, qx, fmaf(qy, qy, qz * qz))));
        if (piv < 0.0f) invn = -invn;

        int idx = t * V_ + v;
        ((float4*)out)[idx] = make_float4(qw * invn, qx * invn, qy * invn, qz * invn);
        outt[idx * 3 + 0] = dx - cx;
        outt[idx * 3 + 1] = dy - cy;
        outt[idx * 3 + 2] = dz - cz;
    }
}

extern "C" void kernel_launch(void* const* d_in, const int* in_sizes, int n_in,
                              void* d_out, int out_size) {
    const float* can = (const float*)d_in[0];
    const float* def = (const float*)d_in[1];
    const int* nbr = (const int*)d_in[2];
    const void* mask = d_in[3];
    float* out = (float*)d_out;

    static int smem_set = 0;
    const int smem_bytes = 6 * V_ * (int)sizeof(float);  // 120,552 B
    if (!smem_set) {
        cudaFuncSetAttribute(se3_frame_kernel,
                             cudaFuncAttributeMaxDynamicSharedMemorySize, smem_bytes);
        smem_set = 1;
    }

    se3_frame_kernel<<<T_, THREADS, smem_bytes>>>(can, def, nbr, mask, out);
}

// round 13
// speedup vs baseline: 1.0457x; 1.0457x over previous
#include <cuda_runtime.h>
#include <cstdint>

#define T_ 128
#define V_ 5023
#define K_ 16
#define NTV (T_ * V_)
#define THREADS 1024

__device__ float g_dummy[4];

extern __shared__ float s_rec[];  // [6 * V_] : {can.xyz, def.xyz} per vertex

// Full rotation epilogue from cross-covariance A (A[i][j] = sum q_i p_j).
// Writes quaternion (w,x,y,z) to dst.
__device__ __forceinline__ void rot_epilogue(
    float A00, float A01, float A02,
    float A10, float A11, float A12,
    float A20, float A21, float A22,
    float4* __restrict__ dst) {
    // Davenport K matrix (symmetric, trace 0)
    float k00 = A00 + A11 + A22;
    float k11 = A00 - A11 - A22;
    float k22 = -A00 + A11 - A22;
    float k33 = -A00 - A11 + A22;
    float k01 = A21 - A12;
    float k02 = A02 - A20;
    float k03 = A10 - A01;
    float k12 = A01 + A10;
    float k13 = A02 + A20;
    float k23 = A12 + A21;

    // characteristic quartic f(x) = x^4 + c2 x^2 + c1 x + c0
    float trAtA = A00 * A00 + A01 * A01 + A02 * A02 +
                  A10 * A10 + A11 * A11 + A12 * A12 +
                  A20 * A20 + A21 * A21 + A22 * A22;
    float c2 = -2.0f * trAtA;
    float detA = A00 * (A11 * A22 - A12 * A21)
               - A01 * (A10 * A22 - A12 * A20)
               + A02 * (A10 * A21 - A11 * A20);
    float c1 = -8.0f * detA;
    float M0 = k11 * (k22 * k33 - k23 * k23)
             - k12 * (k12 * k33 - k23 * k13)
             + k13 * (k12 * k23 - k22 * k13);
    float M1 = k01 * (k22 * k33 - k23 * k23)
             - k12 * (k02 * k33 - k23 * k03)
             + k13 * (k02 * k23 - k22 * k03);
    float M2 = k01 * (k12 * k33 - k23 * k13)
             - k11 * (k02 * k33 - k23 * k03)
             + k13 * (k02 * k13 - k12 * k03);
    float M3 = k01 * (k12 * k23 - k22 * k13)
             - k11 * (k02 * k23 - k22 * k03)
             + k12 * (k02 * k13 - k12 * k03);
    float c0 = k00 * M0 - k01 * M1 + k02 * M2 - k03 * M3;

    // Newton from upper bound sqrt(3 trAtA) >= lam_max
    float lam = 1.7320508f * sqrtf(trAtA);
    float fp2 = 1.0f;
#pragma unroll
    for (int it = 0; it < 9; it++) {
        float lam2 = lam * lam;
        float f = (lam2 + c2) * lam2 + fmaf(c1, lam, c0);
        fp2 = fmaf(4.0f * lam2 + 2.0f * c2, lam, c1);
        lam -= __fdividef(f, fp2);
    }

    // eigenvector: column 0 of M = B^3 + a3 B^2 + a2 B + a1 I
    float b00 = k00 - lam, b11 = k11 - lam, b22 = k22 - lam, b33 = k33 - lam;
    float a3 = 4.0f * lam;
    float a2 = fmaf(6.0f * lam, lam, c2);
    float a1 = fp2;

    float u10 = b00, u11 = k01, u12 = k02, u13 = k03;
    float u20 = b00 * u10 + k01 * u11 + k02 * u12 + k03 * u13;
    float u21 = k01 * u10 + b11 * u11 + k12 * u12 + k13 * u13;
    float u22 = k02 * u10 + k12 * u11 + b22 * u12 + k23 * u13;
    float u23 = k03 * u10 + k13 * u11 + k23 * u12 + b33 * u13;
    float u30 = b00 * u20 + k01 * u21 + k02 * u22 + k03 * u23;
    float u31 = k01 * u20 + b11 * u21 + k12 * u22 + k13 * u23;
    float u32 = k02 * u20 + k12 * u21 + b22 * u22 + k23 * u23;
    float u33 = k03 * u20 + k13 * u21 + k23 * u22 + b33 * u23;

    float qw = u30 + a3 * u20 + a2 * u10 + a1;
    float qx = u31 + a3 * u21 + a2 * u11;
    float qy = u32 + a3 * u22 + a2 * u12;
    float qz = u33 + a3 * u23 + a2 * u13;

    float nq = fmaf(qw, qw, fmaf(qx, qx, fmaf(qy, qy, qz * qz)));
    if (nq < 1e-4f * a1 * a1) {
        // rare fallback (near-180-degree rotation): full adjugate, best column
        float C00 = b00 * b00 + k01 * k01 + k02 * k02 + k03 * k03;
        float C01 = b00 * k01 + k01 * b11 + k02 * k12 + k03 * k13;
        float C02 = b00 * k02 + k01 * k12 + k02 * b22 + k03 * k23;
        float C03 = b00 * k03 + k01 * k13 + k02 * k23 + k03 * b33;
        float C11 = k01 * k01 + b11 * b11 + k12 * k12 + k13 * k13;
        float C12 = k01 * k02 + b11 * k12 + k12 * b22 + k13 * k23;
        float C13 = k01 * k03 + b11 * k13 + k12 * k23 + k13 * b33;
        float C22 = k02 * k02 + k12 * k12 + b22 * b22 + k23 * k23;
        float C23 = k02 * k03 + k12 * k13 + b22 * k23 + k23 * b33;
        float C33 = k03 * k03 + k13 * k13 + k23 * k23 + b33 * b33;
        float P01v = b00 * C01 + k01 * C11 + k02 * C12 + k03 * C13;
        float P02v = b00 * C02 + k01 * C12 + k02 * C22 + k03 * C23;
        float P03v = b00 * C03 + k01 * C13 + k02 * C23 + k03 * C33;
        float P11v = k01 * C01 + b11 * C11 + k12 * C12 + k13 * C13;
        float P12v = k01 * C02 + b11 * C12 + k12 * C22 + k13 * C23;
        float P13v = k01 * C03 + b11 * C13 + k12 * C23 + k13 * C33;
        float P22v = k02 * C02 + k12 * C12 + b22 * C22 + k23 * C23;
        float P23v = k02 * C03 + k12 * C13 + b22 * C23 + k23 * C33;
        float P33v = k03 * C03 + k13 * C13 + k23 * C23 + b33 * C33;
        float N01 = P01v + a3 * C01 + a2 * k01;
        float N02 = P02v + a3 * C02 + a2 * k02;
        float N03 = P03v + a3 * C03 + a2 * k03;
        float N11 = P11v + a3 * C11 + a2 * b11 + a1;
        float N12 = P12v + a3 * C12 + a2 * k12;
        float N13 = P13v + a3 * C13 + a2 * k13;
        float N22 = P22v + a3 * C22 + a2 * b22 + a1;
        float N23 = P23v + a3 * C23 + a2 * k23;
        float N33 = P33v + a3 * C33 + a2 * b33 + a1;
        float bd = nq > 0 ? sqrtf(nq) : 0.0f;
        if (fabsf(N11) > bd) { bd = fabsf(N11); qw = N01; qx = N11; qy = N12; qz = N13; }
        if (fabsf(N22) > bd) { bd = fabsf(N22); qw = N02; qx = N12; qy = N22; qz = N23; }
        if (fabsf(N33) > bd) { qw = N03; qx = N13; qy = N23; qz = N33; }
    }

    // sign convention: component with largest |value| (w,x,y,z, first on ties) positive
    float aw = fabsf(qw), ax = fabsf(qx), ay = fabsf(qy), az = fabsf(qz);
    float besta = aw, piv = qw;
    if (ax > besta) { besta = ax; piv = qx; }
    if (ay > besta) { besta = ay; piv = qy; }
    if (az > besta) { besta = az; piv = qz; }
    float invn = rsqrtf(fmaf(qw, qw, fmaf(qx, qx, fmaf(qy, qy, qz * qz))));
    if (piv < 0.0f) invn = -invn;

    *dst = make_float4(qw * invn, qx * invn, qy * invn, qz * invn);
}

__global__ void __launch_bounds__(THREADS)
se3_frame_kernel(const float* __restrict__ can, const float* __restrict__ def,
                 const int* __restrict__ nbr, const void* __restrict__ maskp,
                 float* __restrict__ out) {
    const int t = blockIdx.x;
    const int tid = threadIdx.x;
    const float* canT = can + (size_t)t * (V_ * 3);
    const float* defT = def + (size_t)t * (V_ * 3);

    __shared__ int s_mode;  // 0 = uint8 bool, 1 = int32, 2 = float32

    if (tid < 32) {
        unsigned int x = ((const unsigned int*)maskp)[tid];
        bool weird = (x != 0u) && (x != 1u) && (x != 0x3F800000u);
        bool isf32 = (x == 0x3F800000u);
        unsigned bp = __ballot_sync(0xffffffffu, weird);
        unsigned fp = __ballot_sync(0xffffffffu, isf32);
        if (tid == 0) s_mode = bp ? 0 : (fp ? 2 : 1);
    }

    // stage this frame's positions into smem as packed 24B records
    for (int v = tid; v < V_; v += THREADS) {
        int b = 3 * v;
        float* r = s_rec + 6 * v;
        r[0] = canT[b]; r[1] = canT[b + 1]; r[2] = canT[b + 2];
        r[3] = defT[b]; r[4] = defT[b + 1]; r[5] = defT[b + 2];
    }
    __syncthreads();

    const int mode = s_mode;
    float* outt = out + (size_t)NTV * 4;

    // software pipeline state: previous vertex's covariance + output slot
    float pA00 = 1, pA01 = 0, pA02 = 0;
    float pA10 = 0, pA11 = 1, pA12 = 0;
    float pA20 = 0, pA21 = 0, pA22 = 1;
    int pidx = -1;

#pragma unroll 1
    for (int v = tid; v < V_; v += THREADS) {
        // ---- active-neighbor bitmask (dtype-robust; uniform branch) ----
        unsigned int amask = 0;
        if (mode == 0) {
            uint4 mw = *(const uint4*)((const unsigned char*)maskp + (size_t)v * K_);
            unsigned int ws[4] = {mw.x, mw.y, mw.z, mw.w};
#pragma unroll
            for (int i = 0; i < K_; i++)
                if ((ws[i >> 2] >> ((i & 3) * 8)) & 0xFF) amask |= (1u << i);
        } else if (mode == 1) {
            const int4* mi = (const int4*)((const int*)maskp + (size_t)v * K_);
#pragma unroll
            for (int c = 0; c < 4; c++) {
                int4 x = mi[c];
                if (x.x) amask |= 1u << (c * 4 + 0);
                if (x.y) amask |= 1u << (c * 4 + 1);
                if (x.z) amask |= 1u << (c * 4 + 2);
                if (x.w) amask |= 1u << (c * 4 + 3);
            }
        } else {
            const float4* mf = (const float4*)((const float*)maskp + (size_t)v * K_);
#pragma unroll
            for (int c = 0; c < 4; c++) {
                float4 x = mf[c];
                if (x.x != 0.0f) amask |= 1u << (c * 4 + 0);
                if (x.y != 0.0f) amask |= 1u << (c * 4 + 1);
                if (x.z != 0.0f) amask |= 1u << (c * 4 + 2);
                if (x.w != 0.0f) amask |= 1u << (c * 4 + 3);
            }
        }

        const float* rv = s_rec + 6 * v;
        float cx = rv[0], cy = rv[1], cz = rv[2];
        float dx = rv[3], dy = rv[4], dz = rv[5];

        int idx = t * V_ + v;
        // translation store now (frees c,d early)
        outt[idx * 3 + 0] = dx - cx;
        outt[idx * 3 + 1] = dy - cy;
        outt[idx * 3 + 2] = dz - cz;

        // ---- gather: predicated-zero loads, branchless accumulation ----
        // inactive slot: loaded P=Q=0 => p = -c, q = -d (matches reference)
        float A00 = 0, A01 = 0, A02 = 0;
        float A10 = 0, A11 = 0, A12 = 0;
        float A20 = 0, A21 = 0, A22 = 0;
#pragma unroll
        for (int c = 0; c < 4; c++) {
            int4 nbc = ((const int4*)(nbr + (size_t)v * K_))[c];
            unsigned sub = amask >> (c * 4);
#pragma unroll
            for (int kk = 0; kk < 4; kk++) {
                int j = (kk == 0) ? nbc.x : (kk == 1) ? nbc.y : (kk == 2) ? nbc.z : nbc.w;
                bool act = (sub >> kk) & 1u;
                float2 r0 = make_float2(0.f, 0.f);
                float2 r1 = make_float2(0.f, 0.f);
                float2 r2 = make_float2(0.f, 0.f);
                if (act) {
                    const float2* rj = (const float2*)(s_rec + 6 * j);
                    r0 = rj[0]; r1 = rj[1]; r2 = rj[2];
                }
                float px = r0.x - cx, py = r0.y - cy, pz = r1.x - cz;
                float qx = r1.y - dx, qy = r2.x - dy, qz = r2.y - dz;
                A00 = fmaf(qx, px, A00); A01 = fmaf(qx, py, A01); A02 = fmaf(qx, pz, A02);
                A10 = fmaf(qy, px, A10); A11 = fmaf(qy, py, A11); A12 = fmaf(qy, pz, A12);
                A20 = fmaf(qz, px, A20); A21 = fmaf(qz, py, A21); A22 = fmaf(qz, pz, A22);
            }
        }

        // ---- epilogue for PREVIOUS vertex (overlaps current gather) ----
        float4* dst = (pidx < 0) ? (float4*)g_dummy : ((float4*)out) + pidx;
        rot_epilogue(pA00, pA01, pA02, pA10, pA11, pA12, pA20, pA21, pA22, dst);

        pA00 = A00; pA01 = A01; pA02 = A02;
        pA10 = A10; pA11 = A11; pA12 = A12;
        pA20 = A20; pA21 = A21; pA22 = A22;
        pidx = idx;
    }

    // drain: epilogue for the last vertex this thread handled
    if (pidx >= 0) {
        rot_epilogue(pA00, pA01, pA02, pA10, pA11, pA12, pA20, pA21, pA22,
                     ((float4*)out) + pidx);
    }
}

extern "C" void kernel_launch(void* const* d_in, const int* in_sizes, int n_in,
                              void* d_out, int out_size) {
    const float* can = (const float*)d_in[0];
    const float* def = (const float*)d_in[1];
    const int* nbr = (const int*)d_in[2];
    const void* mask = d_in[3];
    float* out = (float*)d_out;

    static int smem_set = 0;
    const int smem_bytes = 6 * V_ * (int)sizeof(float);  // 120,552 B
    if (!smem_set) {
        cudaFuncSetAttribute(se3_frame_kernel,
                             cudaFuncAttributeMaxDynamicSharedMemorySize, smem_bytes);
        smem_set = 1;
    }

    se3_frame_kernel<<<T_, THREADS, smem_bytes>>>(can, def, nbr, mask, out);
}